// round 7
// baseline (speedup 1.0000x reference)
#include <cuda_runtime.h>
#include <cuda_bf16.h>
#include <cstdint>

// p, q: (B=64, N=2048, D=4) fp32 -> scalar chamfer + jet loss.
// bf16 m16n8k16 MMA computes the EXACT (hi+lo)x(hi'+lo') product via K-slot
// layout; BOTH epilogue adds are folded into the MMA C accumulator:
//   MMA1: C = qsq_j  -> row-side values ready to min
//   MMA2: C = psq_i  -> col-side values ready to min
#define BB       64
#define NN       2048
#define TPB      256
#define NWARP    8
#define PROWS    128
#define PANELS   (NN / PROWS)        // 16
#define NBLK     (BB * PANELS)       // 1024 blocks
#define ITILES   (PROWS / 16)        // 8
#define NPASS    4
#define JT_PASS  8                   // 4*8*8 = 256 j-tiles = NN/8
#define FINF     __int_as_float(0x7f800000)

__device__ uint4    g_qB[BB * NN];       // prepped hi/lo-split q (4 comps)
__device__ float    g_qsq[BB * NN];
__device__ unsigned g_colminU[BB * NN];  // global col-min (fkey-encoded)
__device__ float    g_cham[NBLK];
__device__ float4   g_jetp[BB], g_jetq[BB];
__device__ float    g_batch[BB];

__device__ __forceinline__ unsigned split_bf16(float v) {
    unsigned short h = __bfloat16_as_ushort(__float2bfloat16_rn(v));
    float fh = __bfloat162float(__ushort_as_bfloat16(h));
    unsigned short l = __bfloat16_as_ushort(__float2bfloat16_rn(v - fh));
    return ((unsigned)l << 16) | (unsigned)h;
}
// monotone float<->uint map: integer min == float min (exact, order-free)
__device__ __forceinline__ unsigned fkey(float f) {
    unsigned u = __float_as_uint(f);
    return (u & 0x80000000u) ? ~u : (u | 0x80000000u);
}
__device__ __forceinline__ float fdecode(unsigned k) {
    return __uint_as_float((k & 0x80000000u) ? (k ^ 0x80000000u) : ~k);
}
__device__ __forceinline__ void mma_bf16(
    float& d0, float& d1, float& d2, float& d3,
    unsigned a0, unsigned a1, unsigned a2, unsigned a3, unsigned b0,
    float c0, float c1, float c2, float c3)
{
    asm volatile(
        "mma.sync.aligned.m16n8k16.row.col.f32.bf16.bf16.f32 "
        "{%0,%1,%2,%3}, {%4,%5,%6,%7}, {%8,%9}, {%10,%11,%12,%13};\n"
        : "=f"(d0), "=f"(d1), "=f"(d2), "=f"(d3)
        : "r"(a0), "r"(a1), "r"(a2), "r"(a3), "r"(b0), "r"(b0),
          "f"(c0), "f"(c1), "f"(c2), "f"(c3));
}
__device__ __forceinline__ float4 warp_sum4(float4 v) {
    #pragma unroll
    for (int off = 16; off > 0; off >>= 1) {
        v.x += __shfl_down_sync(0xffffffffu, v.x, off);
        v.y += __shfl_down_sync(0xffffffffu, v.y, off);
        v.z += __shfl_down_sync(0xffffffffu, v.z, off);
        v.w += __shfl_down_sync(0xffffffffu, v.w, off);
    }
    return v;
}

// Per batch: split q to bf16 hi/lo once, qsq, init col-min, jet sums.
__global__ __launch_bounds__(TPB) void prep(
    const float4* __restrict__ p, const float4* __restrict__ q)
{
    const int b = blockIdx.x, tid = threadIdx.x, w = tid >> 5, lane = tid & 31;
    __shared__ float4 scr[2 * NWARP];
    float4 jp = make_float4(0.f, 0.f, 0.f, 0.f);
    float4 jq = make_float4(0.f, 0.f, 0.f, 0.f);
    for (int j = tid; j < NN; j += TPB) {
        const float4 v = q[b * NN + j];
        jq.x += v.x; jq.y += v.y; jq.z += v.z; jq.w += v.w;
        g_qsq[b * NN + j] = v.x * v.x + v.y * v.y + v.z * v.z + v.w * v.w;
        g_qB[b * NN + j] = make_uint4(split_bf16(v.x), split_bf16(v.y),
                                      split_bf16(v.z), split_bf16(v.w));
        g_colminU[b * NN + j] = 0xFFFFFFFFu;       // re-init every replay
        const float4 a = p[b * NN + j];
        jp.x += a.x; jp.y += a.y; jp.z += a.z; jp.w += a.w;
    }
    jp = warp_sum4(jp); jq = warp_sum4(jq);
    if (lane == 0) { scr[w] = jp; scr[NWARP + w] = jq; }
    __syncthreads();
    if (tid == 0) {
        float4 sp = scr[0], sq = scr[NWARP];
        #pragma unroll
        for (int k = 1; k < NWARP; k++) {
            sp.x += scr[k].x; sp.y += scr[k].y; sp.z += scr[k].z; sp.w += scr[k].w;
            sq.x += scr[NWARP + k].x; sq.y += scr[NWARP + k].y;
            sq.z += scr[NWARP + k].z; sq.w += scr[NWARP + k].w;
        }
        g_jetp[b] = sp; g_jetq[b] = sq;
    }
}

__global__ __launch_bounds__(TPB, 4) void chamfer_bf16(
    const float4* __restrict__ p)
{
    __shared__ __align__(16) unsigned sA[PROWS * 4];   // -2p hi/lo bf16x2
    __shared__ __align__(16) unsigned sB[NN * 4];      // q   hi/lo bf16x2
    __shared__ __align__(16) float    sQsq[NN];
    __shared__ __align__(16) float    sPsq[PROWS];
    __shared__ __align__(16) unsigned sRowMin[PROWS];
    __shared__ float sRed[NWARP];

    const int panel = blockIdx.x, b = blockIdx.y, blk = b * PANELS + panel;
    const int tid = threadIdx.x, w = tid >> 5, lane = tid & 31;
    const int g = lane >> 2, t4 = lane & 3;

    // ---- stage: p rows (convert), prepped q (copy) ----
    if (tid < PROWS) {
        const float4 a = p[b * NN + panel * PROWS + tid];
        sPsq[tid] = a.x * a.x + a.y * a.y + a.z * a.z + a.w * a.w;
        sA[tid * 4 + 0] = split_bf16(-2.f * a.x);
        sA[tid * 4 + 1] = split_bf16(-2.f * a.y);
        sA[tid * 4 + 2] = split_bf16(-2.f * a.z);
        sA[tid * 4 + 3] = split_bf16(-2.f * a.w);
        sRowMin[tid] = 0xFFFFFFFFu;
    }
    for (int j = tid; j < NN; j += TPB) {
        *reinterpret_cast<uint4*>(&sB[j * 4]) = g_qB[b * NN + j];
        sQsq[j] = g_qsq[b * NN + j];
    }
    __syncthreads();

    // ---- main sweep ----
    for (int ps = 0; ps < NPASS; ps++) {
        const int jtbase = ps * (NWARP * JT_PASS) + w * JT_PASS;
        float colA[JT_PASS], colB[JT_PASS];
        #pragma unroll
        for (int jj = 0; jj < JT_PASS; jj++) { colA[jj] = FINF; colB[jj] = FINF; }

        for (int it = 0; it < ITILES; it++) {
            const int r0 = it * 16 + g;
            const unsigned a0 = sA[r0 * 4 + t4];
            const unsigned a1 = sA[(r0 + 8) * 4 + t4];
            const unsigned a2 = __funnelshift_l(a0, a0, 16);  // swapped K half
            const unsigned a3 = __funnelshift_l(a1, a1, 16);
            const float psq0 = sPsq[r0], psq1 = sPsq[r0 + 8];
            float rA0 = FINF, rB0 = FINF, rA1 = FINF, rB1 = FINF;

            #pragma unroll
            for (int jj = 0; jj < JT_PASS; jj++) {
                const int n8 = (jtbase + jj) * 8;
                const unsigned b0 = sB[(n8 + g) * 4 + t4];
                const float2 qq = *reinterpret_cast<const float2*>(&sQsq[n8 + 2 * t4]);
                float d0, d1, d2, d3, e0, e1, e2, e3;
                mma_bf16(d0, d1, d2, d3, a0, a1, a2, a3, b0,
                         qq.x, qq.y, qq.x, qq.y);           // qsq_j - 2p.q
                mma_bf16(e0, e1, e2, e3, a0, a1, a2, a3, b0,
                         psq0, psq0, psq1, psq1);           // psq_i - 2p.q
                rA0 = fminf(rA0, d0); rB0 = fminf(rB0, d1);
                rA1 = fminf(rA1, d2); rB1 = fminf(rB1, d3);
                colA[jj] = fminf(colA[jj], fminf(e0, e2));
                colB[jj] = fminf(colB[jj], fminf(e1, e3));
            }
            float m0 = fminf(rA0, rB0), m1 = fminf(rA1, rB1);
            m0 = fminf(m0, __shfl_xor_sync(0xffffffffu, m0, 1));
            m0 = fminf(m0, __shfl_xor_sync(0xffffffffu, m0, 2));
            m1 = fminf(m1, __shfl_xor_sync(0xffffffffu, m1, 1));
            m1 = fminf(m1, __shfl_xor_sync(0xffffffffu, m1, 2));
            if (t4 == 0) {
                atomicMin(&sRowMin[r0], fkey(m0));
                atomicMin(&sRowMin[r0 + 8], fkey(m1));
            }
        }
        // col-min -> global integer atomicMin (exact, order-independent)
        #pragma unroll
        for (int jj = 0; jj < JT_PASS; jj++) {
            float c0 = colA[jj], c1 = colB[jj];
            c0 = fminf(c0, __shfl_xor_sync(0xffffffffu, c0, 4));
            c0 = fminf(c0, __shfl_xor_sync(0xffffffffu, c0, 8));
            c0 = fminf(c0, __shfl_xor_sync(0xffffffffu, c0, 16));
            c1 = fminf(c1, __shfl_xor_sync(0xffffffffu, c1, 4));
            c1 = fminf(c1, __shfl_xor_sync(0xffffffffu, c1, 8));
            c1 = fminf(c1, __shfl_xor_sync(0xffffffffu, c1, 16));
            if (g == 0) {
                const int col = (jtbase + jj) * 8 + 2 * t4;
                atomicMin(&g_colminU[b * NN + col],     fkey(c0));
                atomicMin(&g_colminU[b * NN + col + 1], fkey(c1));
            }
        }
    }

    // ---- row-side block sum: psq + decoded row-min ----
    __syncthreads();
    float local = (tid < PROWS) ? (sPsq[tid] + fdecode(sRowMin[tid])) : 0.f;
    #pragma unroll
    for (int off = 16; off > 0; off >>= 1)
        local += __shfl_down_sync(0xffffffffu, local, off);
    if (lane == 0) sRed[w] = local;
    __syncthreads();
    if (tid == 0) {
        float s = 0.f;
        #pragma unroll
        for (int k = 0; k < NWARP; k++) s += sRed[k];
        g_cham[blk] = s;
    }
}

// Per batch: col-side sum (qsq + global col-min) + jet term.
__global__ __launch_bounds__(256) void finalize1()
{
    const int b = blockIdx.x, tid = threadIdx.x;
    float local = 0.f;
    for (int j = tid; j < NN; j += 256)
        local += g_qsq[b * NN + j] + fdecode(g_colminU[b * NN + j]);
    if (tid == 0) {
        const float4 sp = g_jetp[b], sq = g_jetq[b];
        const float dx = sp.x - sq.x, dy = sp.y - sq.y;
        const float dz = sp.z - sq.z, dw = sp.w - sq.w;
        local += dx * dx + dy * dy + dz * dz + dw * dw;
    }
    __shared__ float sh[256];
    sh[tid] = local;
    __syncthreads();
    #pragma unroll
    for (int off = 128; off > 0; off >>= 1) {
        if (tid < off) sh[tid] += sh[tid + off];
        __syncthreads();
    }
    if (tid == 0) g_batch[b] = sh[0];
}

__global__ __launch_bounds__(256) void finalize2(float* __restrict__ out)
{
    const int tid = threadIdx.x;
    float v = 0.f;
    for (int i = tid; i < BB; i += 256)   v += g_batch[i];
    for (int i = tid; i < NBLK; i += 256) v += g_cham[i];
    __shared__ float sh[256];
    sh[tid] = v;
    __syncthreads();
    #pragma unroll
    for (int off = 128; off > 0; off >>= 1) {
        if (tid < off) sh[tid] += sh[tid + off];
        __syncthreads();
    }
    if (tid == 0) out[0] = sh[0];
}

extern "C" void kernel_launch(void* const* d_in, const int* in_sizes, int n_in,
                              void* d_out, int out_size)
{
    const float4* p = (const float4*)d_in[0];
    const float4* q = (const float4*)d_in[1];
    float* out = (float*)d_out;

    prep<<<BB, TPB>>>(p, q);
    dim3 grid(PANELS, BB);                    // 1024 blocks, 4/SM
    chamfer_bf16<<<grid, TPB>>>(p);
    finalize1<<<BB, 256>>>();
    finalize2<<<1, 256>>>(out);
}

// round 8
// speedup vs baseline: 1.0408x; 1.0408x over previous
#include <cuda_runtime.h>
#include <cuda_bf16.h>
#include <cstdint>

// p, q: (B=64, N=2048, D=4) fp32 -> scalar chamfer + jet loss.
// bf16 m16n8k16 MMA computes the EXACT (hi+lo)x(hi'+lo') product via K-slot
// layout; both epilogue adds folded into the MMA C accumulator:
//   MMA1: C = qsq_j -> row-side ready to min;  MMA2: C = psq_i -> col-side.
#define BB       64
#define NN       2048
#define TPB      256
#define NWARP    8
#define PROWS    128
#define PANELS   (NN / PROWS)        // 16
#define NBLK     (BB * PANELS)       // 1024 blocks
#define ITILES   (PROWS / 16)        // 8
#define NPASS    2
#define JT_PASS  16                  // 2*8*16 = 256 j-tiles = NN/8
#define FINF     __int_as_float(0x7f800000)

__device__ float g_colmin[NBLK * NN];   // per-panel col-min (exclusive stores)
__device__ float g_cham[NBLK];
__device__ float g_batch[BB];
__device__ int   g_count;               // zero-init; reset by last block

__device__ __forceinline__ unsigned split_bf16(float v) {
    unsigned short h = __bfloat16_as_ushort(__float2bfloat16_rn(v));
    float fh = __bfloat162float(__ushort_as_bfloat16(h));
    unsigned short l = __bfloat16_as_ushort(__float2bfloat16_rn(v - fh));
    return ((unsigned)l << 16) | (unsigned)h;
}
// monotone float<->uint map for shared-memory integer atomicMin
__device__ __forceinline__ unsigned fkey(float f) {
    unsigned u = __float_as_uint(f);
    return (u & 0x80000000u) ? ~u : (u | 0x80000000u);
}
__device__ __forceinline__ float fdecode(unsigned k) {
    return __uint_as_float((k & 0x80000000u) ? (k ^ 0x80000000u) : ~k);
}
__device__ __forceinline__ void mma_bf16(
    float& d0, float& d1, float& d2, float& d3,
    unsigned a0, unsigned a1, unsigned a2, unsigned a3, unsigned b0,
    float c0, float c1, float c2, float c3)
{
    asm volatile(
        "mma.sync.aligned.m16n8k16.row.col.f32.bf16.bf16.f32 "
        "{%0,%1,%2,%3}, {%4,%5,%6,%7}, {%8,%9}, {%10,%11,%12,%13};\n"
        : "=f"(d0), "=f"(d1), "=f"(d2), "=f"(d3)
        : "r"(a0), "r"(a1), "r"(a2), "r"(a3), "r"(b0), "r"(b0),
          "f"(c0), "f"(c1), "f"(c2), "f"(c3));
}

__global__ __launch_bounds__(TPB, 3) void chamfer_bf16(
    const float4* __restrict__ p, const float4* __restrict__ q)
{
    __shared__ __align__(16) unsigned sA[PROWS * 4];   // -2p hi/lo bf16x2
    __shared__ __align__(16) unsigned sB[NN * 4];      // q   hi/lo bf16x2
    __shared__ __align__(16) float    sQsq[NN];
    __shared__ __align__(16) float    sPsq[PROWS];
    __shared__ __align__(16) unsigned sRowMin[PROWS];
    __shared__ float sRed[NWARP];

    const int panel = blockIdx.x, b = blockIdx.y, blk = b * PANELS + panel;
    const int tid = threadIdx.x, w = tid >> 5, lane = tid & 31;
    const int g = lane >> 2, t4 = lane & 3;

    // ---- stage: split p panel and full q to bf16 hi/lo in shared ----
    if (tid < PROWS) {
        const float4 a = p[b * NN + panel * PROWS + tid];
        sPsq[tid] = a.x * a.x + a.y * a.y + a.z * a.z + a.w * a.w;
        sA[tid * 4 + 0] = split_bf16(-2.f * a.x);
        sA[tid * 4 + 1] = split_bf16(-2.f * a.y);
        sA[tid * 4 + 2] = split_bf16(-2.f * a.z);
        sA[tid * 4 + 3] = split_bf16(-2.f * a.w);
        sRowMin[tid] = 0xFFFFFFFFu;
    }
    for (int j = tid; j < NN; j += TPB) {
        const float4 v = q[b * NN + j];
        sQsq[j] = v.x * v.x + v.y * v.y + v.z * v.z + v.w * v.w;
        sB[j * 4 + 0] = split_bf16(v.x);
        sB[j * 4 + 1] = split_bf16(v.y);
        sB[j * 4 + 2] = split_bf16(v.z);
        sB[j * 4 + 3] = split_bf16(v.w);
    }
    __syncthreads();

    // ---- main sweep ----
    #pragma unroll
    for (int ps = 0; ps < NPASS; ps++) {
        const int jtbase = ps * (NWARP * JT_PASS) + w * JT_PASS;
        float colA[JT_PASS], colB[JT_PASS];
        #pragma unroll
        for (int jj = 0; jj < JT_PASS; jj++) { colA[jj] = FINF; colB[jj] = FINF; }

        for (int it = 0; it < ITILES; it++) {
            const int r0 = it * 16 + g;
            const unsigned a0 = sA[r0 * 4 + t4];
            const unsigned a1 = sA[(r0 + 8) * 4 + t4];
            const unsigned a2 = __funnelshift_l(a0, a0, 16);  // swapped K half
            const unsigned a3 = __funnelshift_l(a1, a1, 16);
            const float psq0 = sPsq[r0], psq1 = sPsq[r0 + 8];
            float rA0 = FINF, rB0 = FINF, rA1 = FINF, rB1 = FINF;

            #pragma unroll
            for (int jj = 0; jj < JT_PASS; jj++) {
                const int n8 = (jtbase + jj) * 8;
                const unsigned b0 = sB[(n8 + g) * 4 + t4];
                const float2 qq = *reinterpret_cast<const float2*>(&sQsq[n8 + 2 * t4]);
                float d0, d1, d2, d3, e0, e1, e2, e3;
                mma_bf16(d0, d1, d2, d3, a0, a1, a2, a3, b0,
                         qq.x, qq.y, qq.x, qq.y);            // qsq_j - 2p.q
                mma_bf16(e0, e1, e2, e3, a0, a1, a2, a3, b0,
                         psq0, psq0, psq1, psq1);            // psq_i - 2p.q
                rA0 = fminf(rA0, d0); rB0 = fminf(rB0, d1);
                rA1 = fminf(rA1, d2); rB1 = fminf(rB1, d3);
                colA[jj] = fminf(colA[jj], fminf(e0, e2));
                colB[jj] = fminf(colB[jj], fminf(e1, e3));
            }
            float m0 = fminf(rA0, rB0), m1 = fminf(rA1, rB1);
            m0 = fminf(m0, __shfl_xor_sync(0xffffffffu, m0, 1));
            m0 = fminf(m0, __shfl_xor_sync(0xffffffffu, m0, 2));
            m1 = fminf(m1, __shfl_xor_sync(0xffffffffu, m1, 1));
            m1 = fminf(m1, __shfl_xor_sync(0xffffffffu, m1, 2));
            if (t4 == 0) {
                atomicMin(&sRowMin[r0], fkey(m0));
                atomicMin(&sRowMin[r0 + 8], fkey(m1));
            }
        }
        // col-min writeout: exclusive per-block region, plain stores
        #pragma unroll
        for (int jj = 0; jj < JT_PASS; jj++) {
            float c0 = colA[jj], c1 = colB[jj];
            c0 = fminf(c0, __shfl_xor_sync(0xffffffffu, c0, 4));
            c0 = fminf(c0, __shfl_xor_sync(0xffffffffu, c0, 8));
            c0 = fminf(c0, __shfl_xor_sync(0xffffffffu, c0, 16));
            c1 = fminf(c1, __shfl_xor_sync(0xffffffffu, c1, 4));
            c1 = fminf(c1, __shfl_xor_sync(0xffffffffu, c1, 8));
            c1 = fminf(c1, __shfl_xor_sync(0xffffffffu, c1, 16));
            if (g == 0) {
                const int col = (jtbase + jj) * 8 + 2 * t4;
                *reinterpret_cast<float2*>(&g_colmin[blk * NN + col]) =
                    make_float2(c0, c1);
            }
        }
    }

    // ---- row-side block sum: psq + decoded row-min ----
    __syncthreads();
    float local = (tid < PROWS) ? (sPsq[tid] + fdecode(sRowMin[tid])) : 0.f;
    #pragma unroll
    for (int off = 16; off > 0; off >>= 1)
        local += __shfl_down_sync(0xffffffffu, local, off);
    if (lane == 0) sRed[w] = local;
    __syncthreads();
    if (tid == 0) {
        float s = 0.f;
        #pragma unroll
        for (int k = 0; k < NWARP; k++) s += sRed[k];
        g_cham[blk] = s;
    }
}

// One kernel: per-batch col-side sum + jet + row partial combine; last block
// folds all batch values into out[0] (deterministic: fixed-order final sum).
__global__ __launch_bounds__(256) void finalize(
    const float4* __restrict__ p, const float4* __restrict__ q,
    float* __restrict__ out)
{
    const int b = blockIdx.x, tid = threadIdx.x;
    float local = 0.f;
    float4 jd = make_float4(0.f, 0.f, 0.f, 0.f);
    for (int j = tid; j < NN; j += 256) {
        const float4 v = q[b * NN + j];
        const float4 a = p[b * NN + j];
        jd.x += a.x - v.x; jd.y += a.y - v.y;
        jd.z += a.z - v.z; jd.w += a.w - v.w;
        float m = g_colmin[(b * PANELS + 0) * NN + j];
        #pragma unroll
        for (int pn = 1; pn < PANELS; pn++)
            m = fminf(m, g_colmin[(b * PANELS + pn) * NN + j]);
        local += v.x * v.x + v.y * v.y + v.z * v.z + v.w * v.w + m;
    }
    __shared__ float  sh[256];
    __shared__ float4 sj[256];
    sh[tid] = local; sj[tid] = jd;
    __syncthreads();
    #pragma unroll
    for (int off = 128; off > 0; off >>= 1) {
        if (tid < off) {
            sh[tid] += sh[tid + off];
            sj[tid].x += sj[tid + off].x; sj[tid].y += sj[tid + off].y;
            sj[tid].z += sj[tid + off].z; sj[tid].w += sj[tid + off].w;
        }
        __syncthreads();
    }
    __shared__ int sLast;
    if (tid == 0) {
        float s = sh[0];
        const float4 d = sj[0];
        s += d.x * d.x + d.y * d.y + d.z * d.z + d.w * d.w;
        #pragma unroll
        for (int pn = 0; pn < PANELS; pn++) s += g_cham[b * PANELS + pn];
        g_batch[b] = s;
        __threadfence();
        sLast = (atomicAdd(&g_count, 1) == BB - 1);
    }
    __syncthreads();
    if (sLast) {
        float v = (tid < BB) ? g_batch[tid] : 0.f;
        sh[tid] = v;
        __syncthreads();
        #pragma unroll
        for (int off = 128; off > 0; off >>= 1) {
            if (tid < off) sh[tid] += sh[tid + off];
            __syncthreads();
        }
        if (tid == 0) { out[0] = sh[0]; g_count = 0; }
    }
}

extern "C" void kernel_launch(void* const* d_in, const int* in_sizes, int n_in,
                              void* d_out, int out_size)
{
    const float4* p = (const float4*)d_in[0];
    const float4* q = (const float4*)d_in[1];
    float* out = (float*)d_out;

    dim3 grid(PANELS, BB);                    // 1024 blocks, 3/SM
    chamfer_bf16<<<grid, TPB>>>(p, q);
    finalize<<<BB, 256>>>(p, q, out);
}

// round 9
// speedup vs baseline: 1.1624x; 1.1168x over previous
#include <cuda_runtime.h>
#include <cuda_bf16.h>
#include <cstdint>

// p, q: (B=64, N=2048, D=4) fp32 -> scalar chamfer + jet loss.
// bf16 m16n8k16 MMA computes the EXACT (hi+lo)x(hi'+lo') product via K-slot
// layout; both epilogue adds folded into the MMA C accumulator:
//   MMA1: C = qsq_j -> row-side ready to min;  MMA2: C = psq_i -> col-side.
#define BB       64
#define NN       2048
#define TPB      256
#define NWARP    8
#define PROWS    128
#define PANELS   (NN / PROWS)        // 16
#define NBLK     (BB * PANELS)       // 1024 blocks
#define ITILES   (PROWS / 16)        // 8
#define NPASS    2
#define JT_PASS  16                  // 2*8*16 = 256 j-tiles = NN/8
#define NSLICE   8                   // finalize j-slices per batch
#define FINF     __int_as_float(0x7f800000)

__device__ float  g_colmin[NBLK * NN];   // per-panel col-min (exclusive stores)
__device__ float  g_cham[NBLK];
__device__ float  g_slice[BB * NSLICE];  // per (batch,slice) col-side sums
__device__ float4 g_jd[BB * NSLICE];     // per (batch,slice) jet partials
__device__ int    g_count;               // zero-init; reset by last block

__device__ __forceinline__ unsigned split_bf16(float v) {
    unsigned short h = __bfloat16_as_ushort(__float2bfloat16_rn(v));
    float fh = __bfloat162float(__ushort_as_bfloat16(h));
    unsigned short l = __bfloat16_as_ushort(__float2bfloat16_rn(v - fh));
    return ((unsigned)l << 16) | (unsigned)h;
}
// monotone float<->uint map for shared-memory integer atomicMin
__device__ __forceinline__ unsigned fkey(float f) {
    unsigned u = __float_as_uint(f);
    return (u & 0x80000000u) ? ~u : (u | 0x80000000u);
}
__device__ __forceinline__ float fdecode(unsigned k) {
    return __uint_as_float((k & 0x80000000u) ? (k ^ 0x80000000u) : ~k);
}
__device__ __forceinline__ void mma_bf16(
    float& d0, float& d1, float& d2, float& d3,
    unsigned a0, unsigned a1, unsigned a2, unsigned a3, unsigned b0,
    float c0, float c1, float c2, float c3)
{
    asm volatile(
        "mma.sync.aligned.m16n8k16.row.col.f32.bf16.bf16.f32 "
        "{%0,%1,%2,%3}, {%4,%5,%6,%7}, {%8,%9}, {%10,%11,%12,%13};\n"
        : "=f"(d0), "=f"(d1), "=f"(d2), "=f"(d3)
        : "r"(a0), "r"(a1), "r"(a2), "r"(a3), "r"(b0), "r"(b0),
          "f"(c0), "f"(c1), "f"(c2), "f"(c3));
}

__global__ __launch_bounds__(TPB, 3) void chamfer_bf16(
    const float4* __restrict__ p, const float4* __restrict__ q)
{
    __shared__ __align__(16) unsigned sA[PROWS * 4];   // -2p hi/lo bf16x2
    __shared__ __align__(16) unsigned sB[NN * 4];      // q   hi/lo bf16x2
    __shared__ __align__(16) float    sQsq[NN];
    __shared__ __align__(16) float    sPsq[PROWS];
    __shared__ __align__(16) unsigned sRowMin[PROWS];
    __shared__ float sRed[NWARP];

    const int panel = blockIdx.x, b = blockIdx.y, blk = b * PANELS + panel;
    const int tid = threadIdx.x, w = tid >> 5, lane = tid & 31;
    const int g = lane >> 2, t4 = lane & 3;

    // ---- stage: split p panel and full q to bf16 hi/lo in shared ----
    if (tid < PROWS) {
        const float4 a = p[b * NN + panel * PROWS + tid];
        sPsq[tid] = a.x * a.x + a.y * a.y + a.z * a.z + a.w * a.w;
        sA[tid * 4 + 0] = split_bf16(-2.f * a.x);
        sA[tid * 4 + 1] = split_bf16(-2.f * a.y);
        sA[tid * 4 + 2] = split_bf16(-2.f * a.z);
        sA[tid * 4 + 3] = split_bf16(-2.f * a.w);
        sRowMin[tid] = 0xFFFFFFFFu;
    }
    for (int j = tid; j < NN; j += TPB) {
        const float4 v = q[b * NN + j];
        sQsq[j] = v.x * v.x + v.y * v.y + v.z * v.z + v.w * v.w;
        sB[j * 4 + 0] = split_bf16(v.x);
        sB[j * 4 + 1] = split_bf16(v.y);
        sB[j * 4 + 2] = split_bf16(v.z);
        sB[j * 4 + 3] = split_bf16(v.w);
    }
    __syncthreads();

    // ---- main sweep ----
    #pragma unroll
    for (int ps = 0; ps < NPASS; ps++) {
        const int jtbase = ps * (NWARP * JT_PASS) + w * JT_PASS;
        float colA[JT_PASS], colB[JT_PASS];
        #pragma unroll
        for (int jj = 0; jj < JT_PASS; jj++) { colA[jj] = FINF; colB[jj] = FINF; }

        for (int it = 0; it < ITILES; it++) {
            const int r0 = it * 16 + g;
            const unsigned a0 = sA[r0 * 4 + t4];
            const unsigned a1 = sA[(r0 + 8) * 4 + t4];
            const unsigned a2 = __funnelshift_l(a0, a0, 16);  // swapped K half
            const unsigned a3 = __funnelshift_l(a1, a1, 16);
            const float psq0 = sPsq[r0], psq1 = sPsq[r0 + 8];
            float rA0 = FINF, rB0 = FINF, rA1 = FINF, rB1 = FINF;

            #pragma unroll
            for (int jj = 0; jj < JT_PASS; jj++) {
                const int n8 = (jtbase + jj) * 8;
                const unsigned b0 = sB[(n8 + g) * 4 + t4];
                const float2 qq = *reinterpret_cast<const float2*>(&sQsq[n8 + 2 * t4]);
                float d0, d1, d2, d3, e0, e1, e2, e3;
                mma_bf16(d0, d1, d2, d3, a0, a1, a2, a3, b0,
                         qq.x, qq.y, qq.x, qq.y);            // qsq_j - 2p.q
                mma_bf16(e0, e1, e2, e3, a0, a1, a2, a3, b0,
                         psq0, psq0, psq1, psq1);            // psq_i - 2p.q
                rA0 = fminf(rA0, d0); rB0 = fminf(rB0, d1);
                rA1 = fminf(rA1, d2); rB1 = fminf(rB1, d3);
                colA[jj] = fminf(colA[jj], fminf(e0, e2));
                colB[jj] = fminf(colB[jj], fminf(e1, e3));
            }
            float m0 = fminf(rA0, rB0), m1 = fminf(rA1, rB1);
            m0 = fminf(m0, __shfl_xor_sync(0xffffffffu, m0, 1));
            m0 = fminf(m0, __shfl_xor_sync(0xffffffffu, m0, 2));
            m1 = fminf(m1, __shfl_xor_sync(0xffffffffu, m1, 1));
            m1 = fminf(m1, __shfl_xor_sync(0xffffffffu, m1, 2));
            if (t4 == 0) {
                atomicMin(&sRowMin[r0], fkey(m0));
                atomicMin(&sRowMin[r0 + 8], fkey(m1));
            }
        }
        // col-min writeout: exclusive per-block region, plain stores
        #pragma unroll
        for (int jj = 0; jj < JT_PASS; jj++) {
            float c0 = colA[jj], c1 = colB[jj];
            c0 = fminf(c0, __shfl_xor_sync(0xffffffffu, c0, 4));
            c0 = fminf(c0, __shfl_xor_sync(0xffffffffu, c0, 8));
            c0 = fminf(c0, __shfl_xor_sync(0xffffffffu, c0, 16));
            c1 = fminf(c1, __shfl_xor_sync(0xffffffffu, c1, 4));
            c1 = fminf(c1, __shfl_xor_sync(0xffffffffu, c1, 8));
            c1 = fminf(c1, __shfl_xor_sync(0xffffffffu, c1, 16));
            if (g == 0) {
                const int col = (jtbase + jj) * 8 + 2 * t4;
                *reinterpret_cast<float2*>(&g_colmin[blk * NN + col]) =
                    make_float2(c0, c1);
            }
        }
    }

    // ---- row-side block sum: psq + decoded row-min ----
    __syncthreads();
    float local = (tid < PROWS) ? (sPsq[tid] + fdecode(sRowMin[tid])) : 0.f;
    #pragma unroll
    for (int off = 16; off > 0; off >>= 1)
        local += __shfl_down_sync(0xffffffffu, local, off);
    if (lane == 0) sRed[w] = local;
    __syncthreads();
    if (tid == 0) {
        float s = 0.f;
        #pragma unroll
        for (int k = 0; k < NWARP; k++) s += sRed[k];
        g_cham[blk] = s;
    }
}

// Parallel finalize: 512 blocks, one j-column per thread. Each (batch,slice)
// block writes a partial sum + jet partial; the last block combines all
// partials in a fixed order (deterministic) into out[0].
__global__ __launch_bounds__(256) void finalize(
    const float4* __restrict__ p, const float4* __restrict__ q,
    float* __restrict__ out)
{
    const int s = blockIdx.x, b = blockIdx.y, tid = threadIdx.x;
    const int j = s * 256 + tid;                 // one column per thread

    // col-side: min over 16 panel partials (L2-resident, MLP=16) + qsq
    float m = g_colmin[(b * PANELS + 0) * NN + j];
    #pragma unroll
    for (int pn = 1; pn < PANELS; pn++)
        m = fminf(m, g_colmin[(b * PANELS + pn) * NN + j]);
    const float4 v = q[b * NN + j];
    const float4 a = p[b * NN + j];
    float local = v.x * v.x + v.y * v.y + v.z * v.z + v.w * v.w + m;
    float4 jd = make_float4(a.x - v.x, a.y - v.y, a.z - v.z, a.w - v.w);

    __shared__ float  sh[256];
    __shared__ float4 sj[256];
    sh[tid] = local; sj[tid] = jd;
    __syncthreads();
    #pragma unroll
    for (int off = 128; off > 0; off >>= 1) {
        if (tid < off) {
            sh[tid] += sh[tid + off];
            sj[tid].x += sj[tid + off].x; sj[tid].y += sj[tid + off].y;
            sj[tid].z += sj[tid + off].z; sj[tid].w += sj[tid + off].w;
        }
        __syncthreads();
    }
    __shared__ int sLast;
    if (tid == 0) {
        g_slice[b * NSLICE + s] = sh[0];
        g_jd[b * NSLICE + s]    = sj[0];
        __threadfence();
        sLast = (atomicAdd(&g_count, 1) == BB * NSLICE - 1);
    }
    __syncthreads();
    if (sLast) {
        // fixed-order combine: slice sums + per-batch jet squares + row sums
        float acc = 0.f;
        for (int i = tid; i < BB * NSLICE; i += 256) acc += g_slice[i];
        for (int i = tid; i < NBLK; i += 256)        acc += g_cham[i];
        if (tid < BB) {
            float4 d = g_jd[tid * NSLICE];
            #pragma unroll
            for (int k = 1; k < NSLICE; k++) {
                const float4 t = g_jd[tid * NSLICE + k];
                d.x += t.x; d.y += t.y; d.z += t.z; d.w += t.w;
            }
            acc += d.x * d.x + d.y * d.y + d.z * d.z + d.w * d.w;
        }
        sh[tid] = acc;
        __syncthreads();
        #pragma unroll
        for (int off = 128; off > 0; off >>= 1) {
            if (tid < off) sh[tid] += sh[tid + off];
            __syncthreads();
        }
        if (tid == 0) { out[0] = sh[0]; g_count = 0; }
    }
}

extern "C" void kernel_launch(void* const* d_in, const int* in_sizes, int n_in,
                              void* d_out, int out_size)
{
    const float4* p = (const float4*)d_in[0];
    const float4* q = (const float4*)d_in[1];
    float* out = (float*)d_out;

    dim3 grid(PANELS, BB);                    // 1024 blocks, 3/SM
    chamfer_bf16<<<grid, TPB>>>(p, q);
    dim3 fgrid(NSLICE, BB);                   // 512 finalize blocks
    finalize<<<fgrid, 256>>>(p, q, out);
}